// round 1
// baseline (speedup 1.0000x reference)
#include <cuda_runtime.h>
#include <math.h>

#define NSEQ  4096
#define DIMM  1024
#define HEADS 16
#define HD    64
#define WIDTH 512
#define NW    8
#define NST   512
#define KEYW  1024  /* window key length = 2*WIDTH */

// ---------------- scratch (device globals; no allocation) ----------------
__device__ float g_xn[NSEQ*DIMM];
__device__ float g_qkv[NSEQ*3*DIMM];
__device__ float g_q2s[NSEQ*DIMM];
__device__ float g_state_qkv[NST*3*DIMM];
__device__ float g_st[NST*DIMM];
__device__ float g_qfs_raw[NST*DIMM];

__device__ float g_qn_main[HEADS*NSEQ*HD];
__device__ float g_kn_main[HEADS*NSEQ*HD];
__device__ float g_qn_ts[HEADS*NSEQ*HD];
__device__ float g_kn_ts[HEADS*NST*HD];
__device__ float g_qn_ss[HEADS*NST*HD];
__device__ float g_kn_ss[HEADS*NST*HD];
__device__ float g_qn_fs[HEADS*NST*HD];
__device__ float g_kn_fs[HEADS*NST*HD];

__device__ float g_S_main[(size_t)HEADS*NW*WIDTH*KEYW];   // 256 MB
__device__ float g_S_ts[(size_t)HEADS*NSEQ*NST];          // 128 MB
__device__ float g_S_ss[(size_t)HEADS*NST*NST];
__device__ float g_S_fs[(size_t)HEADS*NST*NST];

__device__ float g_attn_out[NSEQ*DIMM];
__device__ float g_ts_out[NSEQ*DIMM];
__device__ float g_state_cat[NST*2*DIMM];
__device__ float g_so[NST*DIMM];
__device__ float g_z[NST*DIMM];

// ---------------- layernorm (optionally + pos bias) ----------------
__global__ void __launch_bounds__(256) ln_kernel(const float* __restrict__ x,
        const float* __restrict__ gamma, const float* __restrict__ pos,
        float* __restrict__ out)
{
    int row = blockIdx.x;
    const float* xr = x + (long)row*DIMM;
    float* orow = out + (long)row*DIMM;
    __shared__ float red[256];
    float s = 0.f, s2 = 0.f;
    for (int i = threadIdx.x; i < DIMM; i += 256) { float v = xr[i]; s += v; s2 += v*v; }
    red[threadIdx.x] = s; __syncthreads();
    for (int o = 128; o; o >>= 1) { if (threadIdx.x < o) red[threadIdx.x] += red[threadIdx.x+o]; __syncthreads(); }
    float mu = red[0] * (1.f/DIMM);
    __syncthreads();
    red[threadIdx.x] = s2; __syncthreads();
    for (int o = 128; o; o >>= 1) { if (threadIdx.x < o) red[threadIdx.x] += red[threadIdx.x+o]; __syncthreads(); }
    float var = red[0] * (1.f/DIMM) - mu*mu;
    float inv = rsqrtf(var + 1e-5f);
    for (int i = threadIdx.x; i < DIMM; i += 256) {
        float v = (xr[i]-mu)*inv*gamma[i];
        if (pos) v += pos[(long)row*DIMM + i];
        orow[i] = v;
    }
}

// ---------------- generic fp32 SGEMM: C[M,N] = A[M,K] @ B[K,N] (+C) ----------------
__global__ void __launch_bounds__(256) sgemm64(const float* __restrict__ A,
        const float* __restrict__ B, float* __restrict__ C,
        int M, int N, int K, int accum)
{
    __shared__ float As[16][68];
    __shared__ float Bs[16][68];
    int tid = threadIdx.x;
    int tx = tid & 15, ty = tid >> 4;
    int m0 = blockIdx.y*64, n0 = blockIdx.x*64;
    float acc[4][4] = {};
    for (int k0 = 0; k0 < K; k0 += 16) {
        #pragma unroll
        for (int t = 0; t < 4; t++) {
            int e = tid + t*256;
            int r = e >> 4, c = e & 15;                 // A tile 64x16
            As[c][r] = A[(long)(m0+r)*K + k0 + c];
        }
        #pragma unroll
        for (int t = 0; t < 4; t++) {
            int e = tid + t*256;
            int r = e >> 6, c = e & 63;                 // B tile 16x64
            Bs[r][c] = B[(long)(k0+r)*N + n0 + c];
        }
        __syncthreads();
        #pragma unroll
        for (int kk = 0; kk < 16; kk++) {
            float a[4], b[4];
            #pragma unroll
            for (int i = 0; i < 4; i++) a[i] = As[kk][ty*4+i];
            #pragma unroll
            for (int j = 0; j < 4; j++) b[j] = Bs[kk][tx*4+j];
            #pragma unroll
            for (int i = 0; i < 4; i++)
                #pragma unroll
                for (int j = 0; j < 4; j++)
                    acc[i][j] += a[i]*b[j];
        }
        __syncthreads();
    }
    #pragma unroll
    for (int i = 0; i < 4; i++)
        #pragma unroll
        for (int j = 0; j < 4; j++) {
            long idx = (long)(m0+ty*4+i)*N + n0+tx*4+j;
            C[idx] = (accum ? C[idx] : 0.f) + acc[i][j];
        }
}

// ---------------- l2norm per (row, head) + per-dim scale; head-major output ----------------
__global__ void norm_heads(const float* __restrict__ src, int srcStride, int colOff,
        int rowOff, const float* __restrict__ scale, float* __restrict__ dst, int nrows)
{
    int row = blockIdx.x, h = blockIdx.y, d = threadIdx.x;
    float v = src[(long)(rowOff+row)*srcStride + colOff + h*HD + d];
    float s = v*v;
    #pragma unroll
    for (int o = 16; o; o >>= 1) s += __shfl_xor_sync(0xffffffffu, s, o);
    __shared__ float sh[2];
    if ((d & 31) == 0) sh[d>>5] = s;
    __syncthreads();
    float inv = 1.f / fmaxf(sqrtf(sh[0]+sh[1]), 1e-12f);
    dst[((long)h*nrows + row)*HD + d] = v*inv*scale[d];
}

// ---------------- QK^T tile (contraction over d=64, K rows may be padded-zero) ----------------
__device__ __forceinline__ void qk_compute(const float* __restrict__ Qblk,
        const float* __restrict__ Kbase, int kRow0, float acc[4][4])
{
    __shared__ float Qs[64][68];
    __shared__ float Ks[64][68];
    int tid = threadIdx.x;
    #pragma unroll
    for (int t = 0; t < 16; t++) {
        int e = tid + t*256;
        int r = e >> 6, c = e & 63;
        Qs[c][r] = Qblk[(long)r*HD + c];
        int kr = kRow0 + r;
        Ks[c][r] = (kr >= 0) ? Kbase[(long)kr*HD + c] : 0.f;
    }
    __syncthreads();
    int tx = tid & 15, ty = tid >> 4;
    #pragma unroll
    for (int kk = 0; kk < 64; kk++) {
        float a[4], b[4];
        #pragma unroll
        for (int i = 0; i < 4; i++) a[i] = Qs[kk][ty*4+i];
        #pragma unroll
        for (int j = 0; j < 4; j++) b[j] = Ks[kk][tx*4+j];
        #pragma unroll
        for (int i = 0; i < 4; i++)
            #pragma unroll
            for (int j = 0; j < 4; j++)
                acc[i][j] += a[i]*b[j];
    }
}

// main windowed attention scores: *8 + bias, causal mask (j > i+512)
__global__ void __launch_bounds__(256) scores_main(const float* __restrict__ qn,
        const float* __restrict__ kn, const float* __restrict__ bias,
        float* __restrict__ S)
{
    int z = blockIdx.z, h = z >> 3, w = z & 7;
    int i0 = blockIdx.y*64, j0 = blockIdx.x*64;
    const float* Qblk = qn + ((long)h*NSEQ + w*WIDTH + i0)*HD;
    const float* Kbase = kn + (long)h*NSEQ*HD;
    float acc[4][4] = {};
    qk_compute(Qblk, Kbase, (w-1)*WIDTH + j0, acc);
    int tx = threadIdx.x & 15, ty = threadIdx.x >> 4;
    const float* bh = bias + (long)h*WIDTH*KEYW;
    float* Sb = S + (long)z*WIDTH*KEYW;
    #pragma unroll
    for (int ii = 0; ii < 4; ii++)
        #pragma unroll
        for (int jj = 0; jj < 4; jj++) {
            int i = i0 + ty*4 + ii, j = j0 + tx*4 + jj;
            float v = acc[ii][jj]*8.f + bh[(long)i*KEYW + j];
            if (j > i + 512) v = -3.402823466e38f;
            Sb[(long)i*KEYW + j] = v;
        }
}

// generic no-bias no-mask scores (per-head)
__global__ void __launch_bounds__(256) scores_nb(const float* __restrict__ Q,
        const float* __restrict__ Kmat, float* __restrict__ S, int M, int L)
{
    int h = blockIdx.z;
    int i0 = blockIdx.y*64, j0 = blockIdx.x*64;
    const float* Qblk = Q + ((long)h*M + i0)*HD;
    const float* Kbase = Kmat + (long)h*L*HD;
    float acc[4][4] = {};
    qk_compute(Qblk, Kbase, j0, acc);
    int tx = threadIdx.x & 15, ty = threadIdx.x >> 4;
    float* Sr = S + (long)h*M*L;
    #pragma unroll
    for (int ii = 0; ii < 4; ii++)
        #pragma unroll
        for (int jj = 0; jj < 4; jj++)
            Sr[(long)(i0+ty*4+ii)*L + j0+tx*4+jj] = acc[ii][jj]*8.f;
}

// ---------------- row softmax (in-place) ----------------
__global__ void __launch_bounds__(256) softmax_rows(float* __restrict__ S, int L)
{
    long row = blockIdx.x;
    float* r = S + row*(long)L;
    __shared__ float red[256];
    int tid = threadIdx.x;
    float m = -3.402823466e38f;
    for (int i = tid; i < L; i += 256) m = fmaxf(m, r[i]);
    red[tid] = m; __syncthreads();
    for (int o = 128; o; o >>= 1) { if (tid < o) red[tid] = fmaxf(red[tid], red[tid+o]); __syncthreads(); }
    m = red[0];
    __syncthreads();
    float s = 0.f;
    for (int i = tid; i < L; i += 256) { float e = expf(r[i]-m); r[i] = e; s += e; }
    red[tid] = s; __syncthreads();
    for (int o = 128; o; o >>= 1) { if (tid < o) red[tid] += red[tid+o]; __syncthreads(); }
    float inv = 1.f / red[0];
    for (int i = tid; i < L; i += 256) r[i] *= inv;
}

// ---------------- P @ V tile (V gathered from qkv-layout, stride 3072, rows<0 -> 0) ----------------
__device__ __forceinline__ void av_compute(const float* __restrict__ Pblk, int L,
        const float* __restrict__ Vbase, int vRow0, float acc[4][4])
{
    __shared__ float Ps[64][68];
    __shared__ float Vs[64][68];
    int tid = threadIdx.x;
    int tx = tid & 15, ty = tid >> 4;
    for (int l0 = 0; l0 < L; l0 += 64) {
        #pragma unroll
        for (int t = 0; t < 16; t++) {
            int e = tid + t*256;
            int r = e >> 6, c = e & 63;
            Ps[r][c] = Pblk[(long)r*L + l0 + c];
            int vr = vRow0 + l0 + r;
            Vs[r][c] = (vr >= 0) ? Vbase[(long)vr*3072 + c] : 0.f;
        }
        __syncthreads();
        #pragma unroll
        for (int kk = 0; kk < 64; kk++) {
            float a[4], b[4];
            #pragma unroll
            for (int i = 0; i < 4; i++) a[i] = Ps[ty*4+i][kk];
            #pragma unroll
            for (int j = 0; j < 4; j++) b[j] = Vs[kk][tx*4+j];
            #pragma unroll
            for (int i = 0; i < 4; i++)
                #pragma unroll
                for (int j = 0; j < 4; j++)
                    acc[i][j] += a[i]*b[j];
        }
        __syncthreads();
    }
}

__global__ void __launch_bounds__(256) av_main(const float* __restrict__ S,
        const float* __restrict__ qkv, float* __restrict__ out)
{
    int z = blockIdx.z, h = z >> 3, w = z & 7;
    int i0 = blockIdx.y*64;
    const float* Pblk = S + ((long)z*WIDTH + i0)*KEYW;
    float acc[4][4] = {};
    av_compute(Pblk, KEYW, qkv + 2048 + h*HD, (w-1)*WIDTH, acc);
    int tx = threadIdx.x & 15, ty = threadIdx.x >> 4;
    #pragma unroll
    for (int ii = 0; ii < 4; ii++)
        #pragma unroll
        for (int jj = 0; jj < 4; jj++)
            out[(long)(w*WIDTH + i0 + ty*4+ii)*DIMM + h*HD + tx*4+jj] = acc[ii][jj];
}

__global__ void __launch_bounds__(256) av_gen(const float* __restrict__ S, int M, int L,
        const float* __restrict__ Vall, int vColOff, int vRow0,
        float* __restrict__ out, int ostride, int oColMul, int oColAdd)
{
    int h = blockIdx.z;
    int i0 = blockIdx.y*64;
    const float* Pblk = S + ((long)h*M + i0)*L;
    float acc[4][4] = {};
    av_compute(Pblk, L, Vall + vColOff + h*HD, vRow0, acc);
    int tx = threadIdx.x & 15, ty = threadIdx.x >> 4;
    #pragma unroll
    for (int ii = 0; ii < 4; ii++)
        #pragma unroll
        for (int jj = 0; jj < 4; jj++)
            out[(long)(i0+ty*4+ii)*ostride + h*oColMul + oColAdd + tx*4+jj] = acc[ii][jj];
}

// ---------------- memories copy: [2][h][512][64] from raw last-block k/v ----------------
__global__ void memories_kernel(const float* __restrict__ qkv, float* __restrict__ out)
{
    int idx = blockIdx.x*256 + threadIdx.x;
    if (idx >= 2*HEADS*WIDTH*HD) return;
    int d = idx & 63;
    int i = (idx >> 6) & 511;
    int h = (idx >> 15) & 15;
    int s = idx >> 19;
    out[idx] = qkv[(long)(3584+i)*3072 + (s ? 2048 : 1024) + h*HD + d];
}

// ---------------- new_states = sig(beta)*(z+b) + (1-sig)*init ----------------
__global__ void newstates_kernel(const float* __restrict__ gz, const float* __restrict__ bg,
        const float* __restrict__ beta, const float* __restrict__ init_state,
        float* __restrict__ out)
{
    int idx = blockIdx.x*256 + threadIdx.x;
    if (idx >= NST*DIMM) return;
    int c = idx & (DIMM-1);
    float sig = 1.f/(1.f+expf(-beta[c]));
    float z = gz[idx] + bg[c];
    out[idx] = sig*z + (1.f-sig)*init_state[idx];
}

// ---------------- host launch ----------------
static float* symaddr(const void* s)
{
    void* p = nullptr;
    cudaGetSymbolAddress(&p, s);
    return (float*)p;
}

extern "C" void kernel_launch(void* const* d_in, const int* in_sizes, int n_in,
                              void* d_out, int out_size)
{
    const float* x       = (const float*)d_in[0];
    const float* bias    = (const float*)d_in[1];
    const float* gamma   = (const float*)d_in[2];
    const float* w_qkv   = (const float*)d_in[3];
    const float* q_scale = (const float*)d_in[4];
    const float* k_scale = (const float*)d_in[5];
    const float* w_out   = (const float*)d_in[6];
    const float* s_gamma = (const float*)d_in[7];
    const float* w_q2s   = (const float*)d_in[8];
    const float* w_qfs   = (const float*)d_in[9];
    const float* w_sqkv  = (const float*)d_in[10];
    const float* init_st = (const float*)d_in[11];
    const float* pos_ids = (const float*)d_in[12];
    const float* w_sout  = (const float*)d_in[13];
    const float* ts_q    = (const float*)d_in[14];
    const float* ts_k    = (const float*)d_in[15];
    const float* ss_q    = (const float*)d_in[16];
    const float* ss_k    = (const float*)d_in[17];
    const float* fs_q    = (const float*)d_in[18];
    const float* fs_k    = (const float*)d_in[19];
    const float* w_gate  = (const float*)d_in[20];
    const float* b_gate  = (const float*)d_in[21];
    const float* beta    = (const float*)d_in[22];
    float* out = (float*)d_out;

    float* xn   = symaddr(g_xn);
    float* qkv  = symaddr(g_qkv);
    float* q2s  = symaddr(g_q2s);
    float* sqkv = symaddr(g_state_qkv);
    float* st   = symaddr(g_st);
    float* qfsr = symaddr(g_qfs_raw);
    float* qnm  = symaddr(g_qn_main);
    float* knm  = symaddr(g_kn_main);
    float* qnts = symaddr(g_qn_ts);
    float* knts = symaddr(g_kn_ts);
    float* qnss = symaddr(g_qn_ss);
    float* knss = symaddr(g_kn_ss);
    float* qnfs = symaddr(g_qn_fs);
    float* knfs = symaddr(g_kn_fs);
    float* Sm   = symaddr(g_S_main);
    float* Sts  = symaddr(g_S_ts);
    float* Sss  = symaddr(g_S_ss);
    float* Sfs  = symaddr(g_S_fs);
    float* aout = symaddr(g_attn_out);
    float* tout = symaddr(g_ts_out);
    float* scat = symaddr(g_state_cat);
    float* so   = symaddr(g_so);
    float* zb   = symaddr(g_z);

    // 1) layernorms
    ln_kernel<<<NSEQ, 256>>>(x, gamma, nullptr, xn);
    ln_kernel<<<NST, 256>>>(init_st, s_gamma, pos_ids, st);

    // 2) projections
    sgemm64<<<dim3(3072/64, NSEQ/64), 256>>>(xn, w_qkv, qkv, NSEQ, 3072, DIMM, 0);
    sgemm64<<<dim3(DIMM/64, NSEQ/64), 256>>>(xn, w_q2s, q2s, NSEQ, DIMM, DIMM, 0);
    sgemm64<<<dim3(3072/64, NST/64), 256>>>(init_st, w_sqkv, sqkv, NST, 3072, DIMM, 0);
    sgemm64<<<dim3(DIMM/64, NST/64), 256>>>(st, w_qfs, qfsr, NST, DIMM, DIMM, 0);

    // 3) l2norm + scale, head-major
    norm_heads<<<dim3(NSEQ, HEADS), 64>>>(qkv, 3072, 0,    0,    q_scale, qnm,  NSEQ);
    norm_heads<<<dim3(NSEQ, HEADS), 64>>>(qkv, 3072, 1024, 0,    k_scale, knm,  NSEQ);
    norm_heads<<<dim3(NSEQ, HEADS), 64>>>(q2s, 1024, 0,    0,    ts_q,    qnts, NSEQ);
    norm_heads<<<dim3(NST,  HEADS), 64>>>(sqkv, 3072, 1024, 0,   ts_k,    knts, NST);
    norm_heads<<<dim3(NST,  HEADS), 64>>>(sqkv, 3072, 0,    0,   ss_q,    qnss, NST);
    norm_heads<<<dim3(NST,  HEADS), 64>>>(sqkv, 3072, 1024, 0,   ss_k,    knss, NST);
    norm_heads<<<dim3(NST,  HEADS), 64>>>(qfsr, 1024, 0,    0,   fs_q,    qnfs, NST);
    norm_heads<<<dim3(NST,  HEADS), 64>>>(qkv,  3072, 1024, 3584, fs_k,   knfs, NST);

    // 4) scores
    scores_main<<<dim3(KEYW/64, WIDTH/64, HEADS*NW), 256>>>(qnm, knm, bias, Sm);
    scores_nb<<<dim3(NST/64, NSEQ/64, HEADS), 256>>>(qnts, knts, Sts, NSEQ, NST);
    scores_nb<<<dim3(NST/64, NST/64, HEADS), 256>>>(qnss, knss, Sss, NST, NST);
    scores_nb<<<dim3(NST/64, NST/64, HEADS), 256>>>(qnfs, knfs, Sfs, NST, NST);

    // 5) softmax
    softmax_rows<<<HEADS*NW*WIDTH, 256>>>(Sm, KEYW);
    softmax_rows<<<HEADS*NSEQ, 256>>>(Sts, NST);
    softmax_rows<<<HEADS*NST, 256>>>(Sss, NST);
    softmax_rows<<<HEADS*NST, 256>>>(Sfs, NST);

    // 6) P @ V
    av_main<<<dim3(1, WIDTH/64, HEADS*NW), 256>>>(Sm, qkv, aout);
    av_gen<<<dim3(1, NSEQ/64, HEADS), 256>>>(Sts, NSEQ, NST, sqkv, 2048, 0,    tout, DIMM,   64, 0);
    av_gen<<<dim3(1, NST/64, HEADS), 256>>>(Sss, NST,  NST, sqkv, 2048, 0,    scat, 2*DIMM, 128, 0);
    av_gen<<<dim3(1, NST/64, HEADS), 256>>>(Sfs, NST,  NST, qkv,  2048, 3584, scat, 2*DIMM, 128, 64);

    // 7) output projections: out = [attn_out | ts_out] @ w_out
    sgemm64<<<dim3(DIMM/64, NSEQ/64), 256>>>(aout, w_out, out, NSEQ, DIMM, DIMM, 0);
    sgemm64<<<dim3(DIMM/64, NSEQ/64), 256>>>(tout, w_out + (long)DIMM*DIMM, out, NSEQ, DIMM, DIMM, 1);

    // 8) memories
    memories_kernel<<<(2*HEADS*WIDTH*HD)/256, 256>>>(qkv, out + (long)NSEQ*DIMM);

    // 9) state output path
    sgemm64<<<dim3(DIMM/64, NST/64), 256>>>(scat, w_sout, so, NST, DIMM, 2*DIMM, 0);
    sgemm64<<<dim3(DIMM/64, NST/64), 256>>>(so, w_gate, zb, NST, DIMM, DIMM, 0);
    newstates_kernel<<<(NST*DIMM)/256, 256>>>(zb, b_gate, beta, init_st,
            out + (long)NSEQ*DIMM + 2*HEADS*WIDTH*HD);
}

// round 2
// speedup vs baseline: 1.2680x; 1.2680x over previous
#include <cuda_runtime.h>
#include <math.h>

#define NSEQ  4096
#define DIMM  1024
#define HEADS 16
#define HD    64
#define WIDTH 512
#define NW    8
#define NST   512
#define KEYW  1024

// ---------------- scratch (device globals; no allocation) ----------------
__device__ float g_xn[NSEQ*DIMM];
__device__ float g_qkv[NSEQ*3*DIMM];
__device__ float g_q2s[NSEQ*DIMM];
__device__ float g_state_qkv[NST*3*DIMM];
__device__ float g_st[NST*DIMM];
__device__ float g_qfs_raw[NST*DIMM];

__device__ float g_qn_main[HEADS*NSEQ*HD];
__device__ float g_kn_main[HEADS*NSEQ*HD];
__device__ float g_qn_ts[HEADS*NSEQ*HD];
__device__ float g_kn_ts[HEADS*NST*HD];
__device__ float g_qn_ss[HEADS*NST*HD];
__device__ float g_kn_ss[HEADS*NST*HD];
__device__ float g_qn_fs[HEADS*NST*HD];
__device__ float g_kn_fs[HEADS*NST*HD];

__device__ float g_attn_out[NSEQ*DIMM];
__device__ float g_ts_out[NSEQ*DIMM];
__device__ float g_state_cat[NST*2*DIMM];
__device__ float g_so[NST*DIMM];
__device__ float g_z[NST*DIMM];

// ---------------- layernorm (optionally + pos bias) ----------------
__global__ void __launch_bounds__(256) ln_kernel(const float* __restrict__ x,
        const float* __restrict__ gamma, const float* __restrict__ pos,
        float* __restrict__ out)
{
    int row = blockIdx.x;
    const float* xr = x + (long)row*DIMM;
    float* orow = out + (long)row*DIMM;
    __shared__ float red[256];
    float s = 0.f, s2 = 0.f;
    for (int i = threadIdx.x; i < DIMM; i += 256) { float v = xr[i]; s += v; s2 += v*v; }
    red[threadIdx.x] = s; __syncthreads();
    for (int o = 128; o; o >>= 1) { if (threadIdx.x < o) red[threadIdx.x] += red[threadIdx.x+o]; __syncthreads(); }
    float mu = red[0] * (1.f/DIMM);
    __syncthreads();
    red[threadIdx.x] = s2; __syncthreads();
    for (int o = 128; o; o >>= 1) { if (threadIdx.x < o) red[threadIdx.x] += red[threadIdx.x+o]; __syncthreads(); }
    float var = red[0] * (1.f/DIMM) - mu*mu;
    float inv = rsqrtf(var + 1e-5f);
    for (int i = threadIdx.x; i < DIMM; i += 256) {
        float v = (xr[i]-mu)*inv*gamma[i];
        if (pos) v += pos[(long)row*DIMM + i];
        orow[i] = v;
    }
}

// ---------------- 128x128 double-buffered fp32 SGEMM ----------------
__global__ void __launch_bounds__(256) sgemm128(const float* __restrict__ A,
        const float* __restrict__ B, float* __restrict__ C,
        int M, int N, int K, int accum)
{
    __shared__ float As[2][8][128];
    __shared__ float Bs[2][8][128];
    int tid = threadIdx.x;
    int tx = tid & 15, ty = tid >> 4;
    int m0 = blockIdx.y*128, n0 = blockIdx.x*128;

    int arow = tid >> 1;            // 0..127
    int acol = (tid & 1) * 4;       // 0 or 4
    int brow = tid >> 5;            // 0..7
    int bcol = (tid & 31) * 4;      // 0..124

    const float* Aptr = A + (long)(m0 + arow)*K + acol;
    const float* Bptr = B + (long)brow*N + n0 + bcol;

    float acc[8][8];
    #pragma unroll
    for (int i = 0; i < 8; i++)
        #pragma unroll
        for (int j = 0; j < 8; j++) acc[i][j] = 0.f;

    float4 av = *(const float4*)Aptr;
    float4 bv = *(const float4*)Bptr;
    As[0][acol+0][arow]=av.x; As[0][acol+1][arow]=av.y;
    As[0][acol+2][arow]=av.z; As[0][acol+3][arow]=av.w;
    *(float4*)&Bs[0][brow][bcol] = bv;
    __syncthreads();

    int nk = K >> 3;
    for (int kt = 0; kt < nk; kt++) {
        int cur = kt & 1, nxt = cur ^ 1;
        if (kt + 1 < nk) {
            av = *(const float4*)(Aptr + (kt+1)*8);
            bv = *(const float4*)(Bptr + (long)(kt+1)*8*N);
        }
        #pragma unroll
        for (int kk = 0; kk < 8; kk++) {
            float a[8], b[8];
            *(float4*)(a)   = *(const float4*)&As[cur][kk][ty*4];
            *(float4*)(a+4) = *(const float4*)&As[cur][kk][64+ty*4];
            *(float4*)(b)   = *(const float4*)&Bs[cur][kk][tx*4];
            *(float4*)(b+4) = *(const float4*)&Bs[cur][kk][64+tx*4];
            #pragma unroll
            for (int i = 0; i < 8; i++)
                #pragma unroll
                for (int j = 0; j < 8; j++)
                    acc[i][j] += a[i]*b[j];
        }
        if (kt + 1 < nk) {
            As[nxt][acol+0][arow]=av.x; As[nxt][acol+1][arow]=av.y;
            As[nxt][acol+2][arow]=av.z; As[nxt][acol+3][arow]=av.w;
            *(float4*)&Bs[nxt][brow][bcol] = bv;
            __syncthreads();
        }
    }

    #pragma unroll
    for (int s0 = 0; s0 < 2; s0++)
        #pragma unroll
        for (int i = 0; i < 4; i++) {
            long r = (long)(m0 + s0*64 + ty*4 + i)*N + n0;
            #pragma unroll
            for (int s1 = 0; s1 < 2; s1++) {
                float4 v;
                v.x = acc[s0*4+i][s1*4+0];
                v.y = acc[s0*4+i][s1*4+1];
                v.z = acc[s0*4+i][s1*4+2];
                v.w = acc[s0*4+i][s1*4+3];
                float* cp = &C[r + s1*64 + tx*4];
                if (accum) { float4 o = *(float4*)cp; v.x+=o.x; v.y+=o.y; v.z+=o.z; v.w+=o.w; }
                *(float4*)cp = v;
            }
        }
}

// ---------------- l2norm per (row, head) + per-dim scale; head-major output ----------------
__global__ void norm_heads(const float* __restrict__ src, int srcStride, int colOff,
        int rowOff, const float* __restrict__ scale, float* __restrict__ dst, int nrows)
{
    int row = blockIdx.x, h = blockIdx.y, d = threadIdx.x;
    float v = src[(long)(rowOff+row)*srcStride + colOff + h*HD + d];
    float s = v*v;
    #pragma unroll
    for (int o = 16; o; o >>= 1) s += __shfl_xor_sync(0xffffffffu, s, o);
    __shared__ float sh[2];
    if ((d & 31) == 0) sh[d>>5] = s;
    __syncthreads();
    float inv = 1.f / fmaxf(sqrtf(sh[0]+sh[1]), 1e-12f);
    dst[((long)h*nrows + row)*HD + d] = v*inv*scale[d];
}

// ---------------- fused flash attention (64-row q tiles, 64-key chunks) ----------------
// Q head-major [H][MQ][64]; K head-major [H][kHeadRows][64] (rows <0 -> zero pad)
// V gathered from Vall: row (kOff + key + vRowExtra), col (vColHeadMul*h + vColAdd + d)
// bias (optional, per-head [512][1024]) implies causal mask j > i_local + 512
__global__ void __launch_bounds__(256) flash64(
        const float* __restrict__ Q, int qHeadRows,
        const float* __restrict__ Kh, int kHeadRows,
        const float* __restrict__ Vall, long vstride, int vColHeadMul, int vColAdd,
        int vRowExtra,
        const float* __restrict__ bias,
        float* __restrict__ Out, long ostride, int oColMul, int oColAdd,
        int L, int nwin)
{
    extern __shared__ float sm[];
    float (*Qs)[68] = (float(*)[68])(sm);
    float (*Ks)[68] = (float(*)[68])(sm + 64*68);
    float (*Vs)[68] = (float(*)[68])(sm + 2*64*68);
    float (*Ps)[68] = (float(*)[68])(sm + 3*64*68);

    int tid = threadIdx.x;
    int tx = tid & 15, ty = tid >> 4;

    int z = blockIdx.y;
    int h = z / nwin, w = z - h*nwin;
    int winw = qHeadRows / nwin;
    int i0 = blockIdx.x*64;                 // local row within window
    int qrow0 = w*winw + i0;                // row within head
    int kOff = (nwin > 1) ? (w-1)*winw : 0;

    const float* Qblk = Q + ((long)h*qHeadRows + qrow0)*64;
    const float* Kbase = Kh + (long)h*kHeadRows*64;
    const float* Vbase = Vall + vColHeadMul*h + vColAdd;
    const float* biasH = bias ? bias + (long)h*WIDTH*KEYW : nullptr;

    // load Q tile transposed: Qs[d][row]
    #pragma unroll
    for (int t = 0; t < 16; t++) {
        int e = tid + t*256;
        int r = e >> 6, c = e & 63;
        Qs[c][r] = Qblk[(long)r*64 + c];
    }

    float m[4], l[4], acc[4][4];
    #pragma unroll
    for (int i = 0; i < 4; i++) {
        m[i] = -3.402823466e38f; l[i] = 0.f;
        #pragma unroll
        for (int j = 0; j < 4; j++) acc[i][j] = 0.f;
    }

    for (int c0 = 0; c0 < L; c0 += 64) {
        // load K chunk transposed (Ks[d][key]) and V chunk (Vs[key][d])
        #pragma unroll
        for (int t = 0; t < 16; t++) {
            int e = tid + t*256;
            int r = e >> 6, cc = e & 63;
            int kr = kOff + c0 + r;
            Ks[cc][r] = (kr >= 0) ? Kbase[(long)kr*64 + cc] : 0.f;
            Vs[r][cc] = (kr >= 0) ? Vbase[(long)(kr + vRowExtra)*vstride + cc] : 0.f;
        }
        __syncthreads();

        // S = Q @ K^T
        float s[4][4];
        #pragma unroll
        for (int i = 0; i < 4; i++)
            #pragma unroll
            for (int j = 0; j < 4; j++) s[i][j] = 0.f;
        #pragma unroll
        for (int kk = 0; kk < 64; kk++) {
            float a[4], b[4];
            #pragma unroll
            for (int i = 0; i < 4; i++) a[i] = Qs[kk][ty*4+i];
            #pragma unroll
            for (int j = 0; j < 4; j++) b[j] = Ks[kk][tx*4+j];
            #pragma unroll
            for (int i = 0; i < 4; i++)
                #pragma unroll
                for (int j = 0; j < 4; j++)
                    s[i][j] += a[i]*b[j];
        }

        // scale + bias + mask
        #pragma unroll
        for (int i = 0; i < 4; i++) {
            int irow = i0 + ty*4 + i;
            #pragma unroll
            for (int j = 0; j < 4; j++) {
                int jcol = c0 + tx*4 + j;
                float v = s[i][j]*8.f;
                if (biasH) {
                    v += biasH[(long)irow*KEYW + jcol];
                    if (jcol > irow + 512) v = -3.402823466e38f;
                }
                s[i][j] = v;
            }
        }

        // online softmax row stats (reduce across the 16 tx lanes in half-warp)
        #pragma unroll
        for (int i = 0; i < 4; i++) {
            float cm = fmaxf(fmaxf(s[i][0], s[i][1]), fmaxf(s[i][2], s[i][3]));
            #pragma unroll
            for (int o = 8; o; o >>= 1) cm = fmaxf(cm, __shfl_xor_sync(0xffffffffu, cm, o));
            float mnew = fmaxf(m[i], cm);
            float corr = __expf(m[i] - mnew);
            l[i] *= corr;
            #pragma unroll
            for (int j = 0; j < 4; j++) acc[i][j] *= corr;
            float rs = 0.f;
            #pragma unroll
            for (int j = 0; j < 4; j++) {
                float p = __expf(s[i][j] - mnew);
                s[i][j] = p;
                rs += p;
            }
            #pragma unroll
            for (int o = 8; o; o >>= 1) rs += __shfl_xor_sync(0xffffffffu, rs, o);
            l[i] += rs;
            m[i] = mnew;
            // stash P
            Ps[ty*4+i][tx*4+0] = s[i][0];
            Ps[ty*4+i][tx*4+1] = s[i][1];
            Ps[ty*4+i][tx*4+2] = s[i][2];
            Ps[ty*4+i][tx*4+3] = s[i][3];
        }
        __syncthreads();

        // acc += P @ V
        #pragma unroll
        for (int kk = 0; kk < 64; kk++) {
            float a[4], b[4];
            #pragma unroll
            for (int i = 0; i < 4; i++) a[i] = Ps[ty*4+i][kk];
            #pragma unroll
            for (int j = 0; j < 4; j++) b[j] = Vs[kk][tx*4+j];
            #pragma unroll
            for (int i = 0; i < 4; i++)
                #pragma unroll
                for (int j = 0; j < 4; j++)
                    acc[i][j] += a[i]*b[j];
        }
        __syncthreads();
    }

    // epilogue: normalize and store
    #pragma unroll
    for (int i = 0; i < 4; i++) {
        float inv = 1.f / l[i];
        long orow = (long)(qrow0 + ty*4 + i)*ostride + h*oColMul + oColAdd + tx*4;
        #pragma unroll
        for (int j = 0; j < 4; j++)
            Out[orow + j] = acc[i][j]*inv;
    }
}

// ---------------- memories copy ----------------
__global__ void memories_kernel(const float* __restrict__ qkv, float* __restrict__ out)
{
    int idx = blockIdx.x*256 + threadIdx.x;
    if (idx >= 2*HEADS*WIDTH*HD) return;
    int d = idx & 63;
    int i = (idx >> 6) & 511;
    int h = (idx >> 15) & 15;
    int s = idx >> 19;
    out[idx] = qkv[(long)(3584+i)*3072 + (s ? 2048 : 1024) + h*HD + d];
}

// ---------------- new_states ----------------
__global__ void newstates_kernel(const float* __restrict__ gz, const float* __restrict__ bg,
        const float* __restrict__ beta, const float* __restrict__ init_state,
        float* __restrict__ out)
{
    int idx = blockIdx.x*256 + threadIdx.x;
    if (idx >= NST*DIMM) return;
    int c = idx & (DIMM-1);
    float sig = 1.f/(1.f+expf(-beta[c]));
    float z = gz[idx] + bg[c];
    out[idx] = sig*z + (1.f-sig)*init_state[idx];
}

// ---------------- host launch ----------------
static float* symaddr(const void* s)
{
    void* p = nullptr;
    cudaGetSymbolAddress(&p, s);
    return (float*)p;
}

#define FLASH_SMEM (4*64*68*4)

extern "C" void kernel_launch(void* const* d_in, const int* in_sizes, int n_in,
                              void* d_out, int out_size)
{
    const float* x       = (const float*)d_in[0];
    const float* bias    = (const float*)d_in[1];
    const float* gamma   = (const float*)d_in[2];
    const float* w_qkv   = (const float*)d_in[3];
    const float* q_scale = (const float*)d_in[4];
    const float* k_scale = (const float*)d_in[5];
    const float* w_out   = (const float*)d_in[6];
    const float* s_gamma = (const float*)d_in[7];
    const float* w_q2s   = (const float*)d_in[8];
    const float* w_qfs   = (const float*)d_in[9];
    const float* w_sqkv  = (const float*)d_in[10];
    const float* init_st = (const float*)d_in[11];
    const float* pos_ids = (const float*)d_in[12];
    const float* w_sout  = (const float*)d_in[13];
    const float* ts_q    = (const float*)d_in[14];
    const float* ts_k    = (const float*)d_in[15];
    const float* ss_q    = (const float*)d_in[16];
    const float* ss_k    = (const float*)d_in[17];
    const float* fs_q    = (const float*)d_in[18];
    const float* fs_k    = (const float*)d_in[19];
    const float* w_gate  = (const float*)d_in[20];
    const float* b_gate  = (const float*)d_in[21];
    const float* beta    = (const float*)d_in[22];
    float* out = (float*)d_out;

    float* xn   = symaddr(g_xn);
    float* qkv  = symaddr(g_qkv);
    float* q2s  = symaddr(g_q2s);
    float* sqkv = symaddr(g_state_qkv);
    float* st   = symaddr(g_st);
    float* qfsr = symaddr(g_qfs_raw);
    float* qnm  = symaddr(g_qn_main);
    float* knm  = symaddr(g_kn_main);
    float* qnts = symaddr(g_qn_ts);
    float* knts = symaddr(g_kn_ts);
    float* qnss = symaddr(g_qn_ss);
    float* knss = symaddr(g_kn_ss);
    float* qnfs = symaddr(g_qn_fs);
    float* knfs = symaddr(g_kn_fs);
    float* aout = symaddr(g_attn_out);
    float* tout = symaddr(g_ts_out);
    float* scat = symaddr(g_state_cat);
    float* so   = symaddr(g_so);
    float* zb   = symaddr(g_z);

    cudaFuncSetAttribute(flash64, cudaFuncAttributeMaxDynamicSharedMemorySize, FLASH_SMEM);

    // 1) layernorms
    ln_kernel<<<NSEQ, 256>>>(x, gamma, nullptr, xn);
    ln_kernel<<<NST, 256>>>(init_st, s_gamma, pos_ids, st);

    // 2) projections
    sgemm128<<<dim3(3072/128, NSEQ/128), 256>>>(xn, w_qkv, qkv, NSEQ, 3072, DIMM, 0);
    sgemm128<<<dim3(DIMM/128, NSEQ/128), 256>>>(xn, w_q2s, q2s, NSEQ, DIMM, DIMM, 0);
    sgemm128<<<dim3(3072/128, NST/128), 256>>>(init_st, w_sqkv, sqkv, NST, 3072, DIMM, 0);
    sgemm128<<<dim3(DIMM/128, NST/128), 256>>>(st, w_qfs, qfsr, NST, DIMM, DIMM, 0);

    // 3) l2norm + scale, head-major
    norm_heads<<<dim3(NSEQ, HEADS), 64>>>(qkv, 3072, 0,    0,    q_scale, qnm,  NSEQ);
    norm_heads<<<dim3(NSEQ, HEADS), 64>>>(qkv, 3072, 1024, 0,    k_scale, knm,  NSEQ);
    norm_heads<<<dim3(NSEQ, HEADS), 64>>>(q2s, 1024, 0,    0,    ts_q,    qnts, NSEQ);
    norm_heads<<<dim3(NST,  HEADS), 64>>>(sqkv, 3072, 1024, 0,   ts_k,    knts, NST);
    norm_heads<<<dim3(NST,  HEADS), 64>>>(sqkv, 3072, 0,    0,   ss_q,    qnss, NST);
    norm_heads<<<dim3(NST,  HEADS), 64>>>(sqkv, 3072, 1024, 0,   ss_k,    knss, NST);
    norm_heads<<<dim3(NST,  HEADS), 64>>>(qfsr, 1024, 0,    0,   fs_q,    qnfs, NST);
    norm_heads<<<dim3(NST,  HEADS), 64>>>(qkv,  3072, 1024, 3584, fs_k,   knfs, NST);

    // 4) fused attentions
    flash64<<<dim3(WIDTH/64, HEADS*NW), 256, FLASH_SMEM>>>(
        qnm, NSEQ, knm, NSEQ, qkv, 3072, HD, 2048, 0, bias,
        aout, DIMM, HD, 0, KEYW, NW);
    flash64<<<dim3(NSEQ/64, HEADS), 256, FLASH_SMEM>>>(
        qnts, NSEQ, knts, NST, sqkv, 3072, HD, 2048, 0, nullptr,
        tout, DIMM, HD, 0, NST, 1);
    flash64<<<dim3(NST/64, HEADS), 256, FLASH_SMEM>>>(
        qnss, NST, knss, NST, sqkv, 3072, HD, 2048, 0, nullptr,
        scat, 2*DIMM, 2*HD, 0, NST, 1);
    flash64<<<dim3(NST/64, HEADS), 256, FLASH_SMEM>>>(
        qnfs, NST, knfs, NST, qkv, 3072, HD, 2048, 3584, nullptr,
        scat, 2*DIMM, 2*HD, HD, NST, 1);

    // 5) output projections: out = [attn_out | ts_out] @ w_out
    sgemm128<<<dim3(DIMM/128, NSEQ/128), 256>>>(aout, w_out, out, NSEQ, DIMM, DIMM, 0);
    sgemm128<<<dim3(DIMM/128, NSEQ/128), 256>>>(tout, w_out + (long)DIMM*DIMM, out, NSEQ, DIMM, DIMM, 1);

    // 6) memories
    memories_kernel<<<(2*HEADS*WIDTH*HD)/256, 256>>>(qkv, out + (long)NSEQ*DIMM);

    // 7) state output path
    sgemm128<<<dim3(DIMM/128, NST/128), 256>>>(scat, w_sout, so, NST, DIMM, 2*DIMM, 0);
    sgemm128<<<dim3(DIMM/128, NST/128), 256>>>(so, w_gate, zb, NST, DIMM, DIMM, 0);
    newstates_kernel<<<(NST*DIMM)/256, 256>>>(zb, b_gate, beta, init_st,
            out + (long)NSEQ*DIMM + 2*HEADS*WIDTH*HD);
}

// round 3
// speedup vs baseline: 1.8327x; 1.4453x over previous
#include <cuda_runtime.h>
#include <math.h>

#define NSEQ  4096
#define DIMM  1024
#define HEADS 16
#define HD    64
#define WIDTH 512
#define NW    8
#define NST   512
#define KEYW  1024

// ---------------- scratch (device globals; no allocation) ----------------
__device__ float g_xn[NSEQ*DIMM];
__device__ float g_qkv[NSEQ*3*DIMM];
__device__ float g_q2s[NSEQ*DIMM];
__device__ float g_state_qkv[NST*3*DIMM];
__device__ float g_st[NST*DIMM];
__device__ float g_qfs_raw[NST*DIMM];

__device__ float g_qn_main[HEADS*NSEQ*HD];
__device__ float g_kn_main[HEADS*NSEQ*HD];
__device__ float g_qn_ts[HEADS*NSEQ*HD];
__device__ float g_kn_ts[HEADS*NST*HD];
__device__ float g_qn_ss[HEADS*NST*HD];
__device__ float g_kn_ss[HEADS*NST*HD];
__device__ float g_qn_fs[HEADS*NST*HD];
__device__ float g_kn_fs[HEADS*NST*HD];

__device__ float g_attn_out[NSEQ*DIMM];
__device__ float g_ts_out[NSEQ*DIMM];
__device__ float g_state_cat[NST*2*DIMM];
__device__ float g_so[NST*DIMM];
__device__ float g_z[NST*DIMM];

// ---------------- layernorm (optionally + pos bias) ----------------
__global__ void __launch_bounds__(256) ln_kernel(const float* __restrict__ x,
        const float* __restrict__ gamma, const float* __restrict__ pos,
        float* __restrict__ out)
{
    int row = blockIdx.x;
    const float* xr = x + (long)row*DIMM;
    float* orow = out + (long)row*DIMM;
    __shared__ float red[256];
    float s = 0.f, s2 = 0.f;
    for (int i = threadIdx.x; i < DIMM; i += 256) { float v = xr[i]; s += v; s2 += v*v; }
    red[threadIdx.x] = s; __syncthreads();
    for (int o = 128; o; o >>= 1) { if (threadIdx.x < o) red[threadIdx.x] += red[threadIdx.x+o]; __syncthreads(); }
    float mu = red[0] * (1.f/DIMM);
    __syncthreads();
    red[threadIdx.x] = s2; __syncthreads();
    for (int o = 128; o; o >>= 1) { if (threadIdx.x < o) red[threadIdx.x] += red[threadIdx.x+o]; __syncthreads(); }
    float var = red[0] * (1.f/DIMM) - mu*mu;
    float inv = rsqrtf(var + 1e-5f);
    for (int i = threadIdx.x; i < DIMM; i += 256) {
        float v = (xr[i]-mu)*inv*gamma[i];
        if (pos) v += pos[(long)row*DIMM + i];
        orow[i] = v;
    }
}

// ---------------- TF32 tensor-core GEMM: C[M,N] = A @ B (+C) ----------------
__device__ __forceinline__ unsigned f2tf32(float f)
{
    unsigned r;
    asm("cvt.rna.tf32.f32 %0, %1;" : "=r"(r) : "f"(f));
    return r;
}

__device__ __forceinline__ void mma_tf32(float c[4], const unsigned a[4], const unsigned b[2])
{
    asm volatile(
        "mma.sync.aligned.m16n8k8.row.col.f32.tf32.tf32.f32 "
        "{%0,%1,%2,%3}, {%4,%5,%6,%7}, {%8,%9}, {%0,%1,%2,%3};"
        : "+f"(c[0]), "+f"(c[1]), "+f"(c[2]), "+f"(c[3])
        : "r"(a[0]), "r"(a[1]), "r"(a[2]), "r"(a[3]), "r"(b[0]), "r"(b[1]));
}

// 128x128 block, BK=16, 8 warps each 32x64, double buffered
__global__ void __launch_bounds__(256) tgemm(const float* __restrict__ A,
        const float* __restrict__ B, float* __restrict__ C,
        int M, int N, int K, int accum)
{
    __shared__ unsigned As[2][16][132];   // [k][m]
    __shared__ unsigned Bs[2][16][132];   // [k][n]

    int tid = threadIdx.x;
    int warp = tid >> 5, lane = tid & 31;
    int wy = warp >> 1, wx = warp & 1;
    int g = lane >> 2, t4 = lane & 3;
    int m0 = blockIdx.y*128, n0 = blockIdx.x*128;

    int arow = tid >> 2;           // 0..63
    int acol = (tid & 3) * 4;      // 0,4,8,12
    int bkrow = tid >> 5;          // 0..7
    int bcol = lane * 4;           // 0..124

    const float* Abase = A + (long)(m0 + arow)*K + acol;
    const float* Bbase = B + (long)bkrow*N + n0 + bcol;

    float acc[2][8][4];
    #pragma unroll
    for (int mi = 0; mi < 2; mi++)
        #pragma unroll
        for (int nj = 0; nj < 8; nj++)
            #pragma unroll
            for (int c = 0; c < 4; c++) acc[mi][nj][c] = 0.f;

    float4 ra0, ra1, rb0, rb1;

    auto ldg = [&](int kt) {
        ra0 = *(const float4*)(Abase + kt*16);
        ra1 = *(const float4*)(Abase + kt*16 + (long)64*K);
        rb0 = *(const float4*)(Bbase + (long)kt*16*N);
        rb1 = *(const float4*)(Bbase + (long)(kt*16+8)*N);
    };
    auto sts = [&](int buf) {
        As[buf][acol+0][arow] = f2tf32(ra0.x);
        As[buf][acol+1][arow] = f2tf32(ra0.y);
        As[buf][acol+2][arow] = f2tf32(ra0.z);
        As[buf][acol+3][arow] = f2tf32(ra0.w);
        As[buf][acol+0][arow+64] = f2tf32(ra1.x);
        As[buf][acol+1][arow+64] = f2tf32(ra1.y);
        As[buf][acol+2][arow+64] = f2tf32(ra1.z);
        As[buf][acol+3][arow+64] = f2tf32(ra1.w);
        Bs[buf][bkrow][bcol+0] = f2tf32(rb0.x);
        Bs[buf][bkrow][bcol+1] = f2tf32(rb0.y);
        Bs[buf][bkrow][bcol+2] = f2tf32(rb0.z);
        Bs[buf][bkrow][bcol+3] = f2tf32(rb0.w);
        Bs[buf][bkrow+8][bcol+0] = f2tf32(rb1.x);
        Bs[buf][bkrow+8][bcol+1] = f2tf32(rb1.y);
        Bs[buf][bkrow+8][bcol+2] = f2tf32(rb1.z);
        Bs[buf][bkrow+8][bcol+3] = f2tf32(rb1.w);
    };

    ldg(0); sts(0);
    __syncthreads();

    int nkt = K >> 4;
    for (int kt = 0; kt < nkt; kt++) {
        int buf = kt & 1;
        if (kt + 1 < nkt) ldg(kt + 1);

        #pragma unroll
        for (int ks = 0; ks < 2; ks++) {
            int kk = ks*8;
            unsigned af[2][4], bf[8][2];
            #pragma unroll
            for (int mi = 0; mi < 2; mi++) {
                int mr = wy*32 + mi*16 + g;
                af[mi][0] = As[buf][kk + t4][mr];
                af[mi][1] = As[buf][kk + t4][mr + 8];
                af[mi][2] = As[buf][kk + t4 + 4][mr];
                af[mi][3] = As[buf][kk + t4 + 4][mr + 8];
            }
            #pragma unroll
            for (int nj = 0; nj < 8; nj++) {
                int nc = wx*64 + nj*8 + g;
                bf[nj][0] = Bs[buf][kk + t4][nc];
                bf[nj][1] = Bs[buf][kk + t4 + 4][nc];
            }
            #pragma unroll
            for (int mi = 0; mi < 2; mi++)
                #pragma unroll
                for (int nj = 0; nj < 8; nj++)
                    mma_tf32(acc[mi][nj], af[mi], bf[nj]);
        }

        if (kt + 1 < nkt) sts(buf ^ 1);
        __syncthreads();
    }

    // epilogue: c0,c1 at (row=g, col=2*t4), c2,c3 at (row=g+8, same col)
    #pragma unroll
    for (int mi = 0; mi < 2; mi++) {
        #pragma unroll
        for (int nj = 0; nj < 8; nj++) {
            int row = m0 + wy*32 + mi*16 + g;
            int col = n0 + wx*64 + nj*8 + t4*2;
            float* p0 = &C[(long)row*N + col];
            float* p1 = &C[(long)(row+8)*N + col];
            float2 v0 = make_float2(acc[mi][nj][0], acc[mi][nj][1]);
            float2 v1 = make_float2(acc[mi][nj][2], acc[mi][nj][3]);
            if (accum) {
                float2 o0 = *(float2*)p0, o1 = *(float2*)p1;
                v0.x += o0.x; v0.y += o0.y; v1.x += o1.x; v1.y += o1.y;
            }
            *(float2*)p0 = v0;
            *(float2*)p1 = v1;
        }
    }
}

// ---------------- l2norm per (row, head) + per-dim scale; head-major output ----------------
__global__ void norm_heads(const float* __restrict__ src, int srcStride, int colOff,
        int rowOff, const float* __restrict__ scale, float* __restrict__ dst, int nrows)
{
    int row = blockIdx.x, h = blockIdx.y, d = threadIdx.x;
    float v = src[(long)(rowOff+row)*srcStride + colOff + h*HD + d];
    float s = v*v;
    #pragma unroll
    for (int o = 16; o; o >>= 1) s += __shfl_xor_sync(0xffffffffu, s, o);
    __shared__ float sh[2];
    if ((d & 31) == 0) sh[d>>5] = s;
    __syncthreads();
    float inv = 1.f / fmaxf(sqrtf(sh[0]+sh[1]), 1e-12f);
    dst[((long)h*nrows + row)*HD + d] = v*inv*scale[d];
}

// ---------------- fused flash attention (64-row q tiles, 64-key chunks) ----------------
__global__ void __launch_bounds__(256) flash64(
        const float* __restrict__ Q, int qHeadRows,
        const float* __restrict__ Kh, int kHeadRows,
        const float* __restrict__ Vall, long vstride, int vColHeadMul, int vColAdd,
        int vRowExtra,
        const float* __restrict__ bias,
        float* __restrict__ Out, long ostride, int oColMul, int oColAdd,
        int L, int nwin)
{
    extern __shared__ float sm[];
    float (*Qs)[68] = (float(*)[68])(sm);
    float (*Ks)[68] = (float(*)[68])(sm + 64*68);
    float (*Vs)[68] = (float(*)[68])(sm + 2*64*68);
    float (*Ps)[68] = (float(*)[68])(sm + 3*64*68);

    int tid = threadIdx.x;
    int tx = tid & 15, ty = tid >> 4;

    int z = blockIdx.y;
    int h = z / nwin, w = z - h*nwin;
    int winw = qHeadRows / nwin;
    int i0 = blockIdx.x*64;
    int qrow0 = w*winw + i0;
    int kOff = (nwin > 1) ? (w-1)*winw : 0;

    const float* Qblk = Q + ((long)h*qHeadRows + qrow0)*64;
    const float* Kbase = Kh + (long)h*kHeadRows*64;
    const float* Vbase = Vall + vColHeadMul*h + vColAdd;
    const float* biasH = bias ? bias + (long)h*WIDTH*KEYW : nullptr;

    #pragma unroll
    for (int t = 0; t < 16; t++) {
        int e = tid + t*256;
        int r = e >> 6, c = e & 63;
        Qs[c][r] = Qblk[(long)r*64 + c];
    }

    float m[4], l[4], acc[4][4];
    #pragma unroll
    for (int i = 0; i < 4; i++) {
        m[i] = -3.402823466e38f; l[i] = 0.f;
        #pragma unroll
        for (int j = 0; j < 4; j++) acc[i][j] = 0.f;
    }

    for (int c0 = 0; c0 < L; c0 += 64) {
        #pragma unroll
        for (int t = 0; t < 16; t++) {
            int e = tid + t*256;
            int r = e >> 6, cc = e & 63;
            int kr = kOff + c0 + r;
            Ks[cc][r] = (kr >= 0) ? Kbase[(long)kr*64 + cc] : 0.f;
            Vs[r][cc] = (kr >= 0) ? Vbase[(long)(kr + vRowExtra)*vstride + cc] : 0.f;
        }
        __syncthreads();

        float s[4][4];
        #pragma unroll
        for (int i = 0; i < 4; i++)
            #pragma unroll
            for (int j = 0; j < 4; j++) s[i][j] = 0.f;
        #pragma unroll
        for (int kk = 0; kk < 64; kk++) {
            float a[4], b[4];
            #pragma unroll
            for (int i = 0; i < 4; i++) a[i] = Qs[kk][ty*4+i];
            #pragma unroll
            for (int j = 0; j < 4; j++) b[j] = Ks[kk][tx*4+j];
            #pragma unroll
            for (int i = 0; i < 4; i++)
                #pragma unroll
                for (int j = 0; j < 4; j++)
                    s[i][j] += a[i]*b[j];
        }

        #pragma unroll
        for (int i = 0; i < 4; i++) {
            int irow = i0 + ty*4 + i;
            #pragma unroll
            for (int j = 0; j < 4; j++) {
                int jcol = c0 + tx*4 + j;
                float v = s[i][j]*8.f;
                if (biasH) {
                    v += biasH[(long)irow*KEYW + jcol];
                    if (jcol > irow + 512) v = -3.402823466e38f;
                }
                s[i][j] = v;
            }
        }

        #pragma unroll
        for (int i = 0; i < 4; i++) {
            float cm = fmaxf(fmaxf(s[i][0], s[i][1]), fmaxf(s[i][2], s[i][3]));
            #pragma unroll
            for (int o = 8; o; o >>= 1) cm = fmaxf(cm, __shfl_xor_sync(0xffffffffu, cm, o));
            float mnew = fmaxf(m[i], cm);
            float corr = __expf(m[i] - mnew);
            l[i] *= corr;
            #pragma unroll
            for (int j = 0; j < 4; j++) acc[i][j] *= corr;
            float rs = 0.f;
            #pragma unroll
            for (int j = 0; j < 4; j++) {
                float p = __expf(s[i][j] - mnew);
                s[i][j] = p;
                rs += p;
            }
            #pragma unroll
            for (int o = 8; o; o >>= 1) rs += __shfl_xor_sync(0xffffffffu, rs, o);
            l[i] += rs;
            m[i] = mnew;
            Ps[ty*4+i][tx*4+0] = s[i][0];
            Ps[ty*4+i][tx*4+1] = s[i][1];
            Ps[ty*4+i][tx*4+2] = s[i][2];
            Ps[ty*4+i][tx*4+3] = s[i][3];
        }
        __syncthreads();

        #pragma unroll
        for (int kk = 0; kk < 64; kk++) {
            float a[4], b[4];
            #pragma unroll
            for (int i = 0; i < 4; i++) a[i] = Ps[ty*4+i][kk];
            #pragma unroll
            for (int j = 0; j < 4; j++) b[j] = Vs[kk][tx*4+j];
            #pragma unroll
            for (int i = 0; i < 4; i++)
                #pragma unroll
                for (int j = 0; j < 4; j++)
                    acc[i][j] += a[i]*b[j];
        }
        __syncthreads();
    }

    #pragma unroll
    for (int i = 0; i < 4; i++) {
        float inv = 1.f / l[i];
        long orow = (long)(qrow0 + ty*4 + i)*ostride + h*oColMul + oColAdd + tx*4;
        #pragma unroll
        for (int j = 0; j < 4; j++)
            Out[orow + j] = acc[i][j]*inv;
    }
}

// ---------------- memories copy ----------------
__global__ void memories_kernel(const float* __restrict__ qkv, float* __restrict__ out)
{
    int idx = blockIdx.x*256 + threadIdx.x;
    if (idx >= 2*HEADS*WIDTH*HD) return;
    int d = idx & 63;
    int i = (idx >> 6) & 511;
    int h = (idx >> 15) & 15;
    int s = idx >> 19;
    out[idx] = qkv[(long)(3584+i)*3072 + (s ? 2048 : 1024) + h*HD + d];
}

// ---------------- new_states ----------------
__global__ void newstates_kernel(const float* __restrict__ gz, const float* __restrict__ bg,
        const float* __restrict__ beta, const float* __restrict__ init_state,
        float* __restrict__ out)
{
    int idx = blockIdx.x*256 + threadIdx.x;
    if (idx >= NST*DIMM) return;
    int c = idx & (DIMM-1);
    float sig = 1.f/(1.f+expf(-beta[c]));
    float z = gz[idx] + bg[c];
    out[idx] = sig*z + (1.f-sig)*init_state[idx];
}

// ---------------- host launch ----------------
static float* symaddr(const void* s)
{
    void* p = nullptr;
    cudaGetSymbolAddress(&p, s);
    return (float*)p;
}

#define FLASH_SMEM (4*64*68*4)

extern "C" void kernel_launch(void* const* d_in, const int* in_sizes, int n_in,
                              void* d_out, int out_size)
{
    const float* x       = (const float*)d_in[0];
    const float* bias    = (const float*)d_in[1];
    const float* gamma   = (const float*)d_in[2];
    const float* w_qkv   = (const float*)d_in[3];
    const float* q_scale = (const float*)d_in[4];
    const float* k_scale = (const float*)d_in[5];
    const float* w_out   = (const float*)d_in[6];
    const float* s_gamma = (const float*)d_in[7];
    const float* w_q2s   = (const float*)d_in[8];
    const float* w_qfs   = (const float*)d_in[9];
    const float* w_sqkv  = (const float*)d_in[10];
    const float* init_st = (const float*)d_in[11];
    const float* pos_ids = (const float*)d_in[12];
    const float* w_sout  = (const float*)d_in[13];
    const float* ts_q    = (const float*)d_in[14];
    const float* ts_k    = (const float*)d_in[15];
    const float* ss_q    = (const float*)d_in[16];
    const float* ss_k    = (const float*)d_in[17];
    const float* fs_q    = (const float*)d_in[18];
    const float* fs_k    = (const float*)d_in[19];
    const float* w_gate  = (const float*)d_in[20];
    const float* b_gate  = (const float*)d_in[21];
    const float* beta    = (const float*)d_in[22];
    float* out = (float*)d_out;

    float* xn   = symaddr(g_xn);
    float* qkv  = symaddr(g_qkv);
    float* q2s  = symaddr(g_q2s);
    float* sqkv = symaddr(g_state_qkv);
    float* st   = symaddr(g_st);
    float* qfsr = symaddr(g_qfs_raw);
    float* qnm  = symaddr(g_qn_main);
    float* knm  = symaddr(g_kn_main);
    float* qnts = symaddr(g_qn_ts);
    float* knts = symaddr(g_kn_ts);
    float* qnss = symaddr(g_qn_ss);
    float* knss = symaddr(g_kn_ss);
    float* qnfs = symaddr(g_qn_fs);
    float* knfs = symaddr(g_kn_fs);
    float* aout = symaddr(g_attn_out);
    float* tout = symaddr(g_ts_out);
    float* scat = symaddr(g_state_cat);
    float* so   = symaddr(g_so);
    float* zb   = symaddr(g_z);

    cudaFuncSetAttribute(flash64, cudaFuncAttributeMaxDynamicSharedMemorySize, FLASH_SMEM);

    // 1) layernorms
    ln_kernel<<<NSEQ, 256>>>(x, gamma, nullptr, xn);
    ln_kernel<<<NST, 256>>>(init_st, s_gamma, pos_ids, st);

    // 2) projections (TF32 tensor cores)
    tgemm<<<dim3(3072/128, NSEQ/128), 256>>>(xn, w_qkv, qkv, NSEQ, 3072, DIMM, 0);
    tgemm<<<dim3(DIMM/128, NSEQ/128), 256>>>(xn, w_q2s, q2s, NSEQ, DIMM, DIMM, 0);
    tgemm<<<dim3(3072/128, NST/128), 256>>>(init_st, w_sqkv, sqkv, NST, 3072, DIMM, 0);
    tgemm<<<dim3(DIMM/128, NST/128), 256>>>(st, w_qfs, qfsr, NST, DIMM, DIMM, 0);

    // 3) l2norm + scale, head-major
    norm_heads<<<dim3(NSEQ, HEADS), 64>>>(qkv, 3072, 0,    0,    q_scale, qnm,  NSEQ);
    norm_heads<<<dim3(NSEQ, HEADS), 64>>>(qkv, 3072, 1024, 0,    k_scale, knm,  NSEQ);
    norm_heads<<<dim3(NSEQ, HEADS), 64>>>(q2s, 1024, 0,    0,    ts_q,    qnts, NSEQ);
    norm_heads<<<dim3(NST,  HEADS), 64>>>(sqkv, 3072, 1024, 0,   ts_k,    knts, NST);
    norm_heads<<<dim3(NST,  HEADS), 64>>>(sqkv, 3072, 0,    0,   ss_q,    qnss, NST);
    norm_heads<<<dim3(NST,  HEADS), 64>>>(sqkv, 3072, 1024, 0,   ss_k,    knss, NST);
    norm_heads<<<dim3(NST,  HEADS), 64>>>(qfsr, 1024, 0,    0,   fs_q,    qnfs, NST);
    norm_heads<<<dim3(NST,  HEADS), 64>>>(qkv,  3072, 1024, 3584, fs_k,   knfs, NST);

    // 4) fused attentions
    flash64<<<dim3(WIDTH/64, HEADS*NW), 256, FLASH_SMEM>>>(
        qnm, NSEQ, knm, NSEQ, qkv, 3072, HD, 2048, 0, bias,
        aout, DIMM, HD, 0, KEYW, NW);
    flash64<<<dim3(NSEQ/64, HEADS), 256, FLASH_SMEM>>>(
        qnts, NSEQ, knts, NST, sqkv, 3072, HD, 2048, 0, nullptr,
        tout, DIMM, HD, 0, NST, 1);
    flash64<<<dim3(NST/64, HEADS), 256, FLASH_SMEM>>>(
        qnss, NST, knss, NST, sqkv, 3072, HD, 2048, 0, nullptr,
        scat, 2*DIMM, 2*HD, 0, NST, 1);
    flash64<<<dim3(NST/64, HEADS), 256, FLASH_SMEM>>>(
        qnfs, NST, knfs, NST, qkv, 3072, HD, 2048, 3584, nullptr,
        scat, 2*DIMM, 2*HD, HD, NST, 1);

    // 5) output projections
    tgemm<<<dim3(DIMM/128, NSEQ/128), 256>>>(aout, w_out, out, NSEQ, DIMM, DIMM, 0);
    tgemm<<<dim3(DIMM/128, NSEQ/128), 256>>>(tout, w_out + (long)DIMM*DIMM, out, NSEQ, DIMM, DIMM, 1);

    // 6) memories
    memories_kernel<<<(2*HEADS*WIDTH*HD)/256, 256>>>(qkv, out + (long)NSEQ*DIMM);

    // 7) state output path
    tgemm<<<dim3(DIMM/128, NST/128), 256>>>(scat, w_sout, so, NST, DIMM, 2*DIMM, 0);
    tgemm<<<dim3(DIMM/128, NST/128), 256>>>(so, w_gate, zb, NST, DIMM, DIMM, 0);
    newstates_kernel<<<(NST*DIMM)/256, 256>>>(zb, b_gate, beta, init_st,
            out + (long)NSEQ*DIMM + 2*HEADS*WIDTH*HD);
}